// round 1
// baseline (speedup 1.0000x reference)
#include <cuda_runtime.h>

#define N_SAMPLES   2048
#define N_CHAN      512
#define HW          49
#define N_GROUPS    64
#define THREADS     256
#define WARPS       (THREADS / 32)

// Scratch accumulators (device globals — no allocation allowed).
__device__ float g_acc[N_GROUPS * N_CHAN];
__device__ int   g_cnt[N_GROUPS];

// Kernel 0: zero the scratch (must run every graph replay).
__global__ void zero_kernel() {
    int i = blockIdx.x * blockDim.x + threadIdx.x;
    if (i < N_GROUPS * N_CHAN) g_acc[i] = 0.0f;
    if (i < N_GROUPS)          g_cnt[i] = 0;
}

// Kernel 1: one block per sample. Each warp reduces whole channels (49
// contiguous floats) and atomically accumulates into the group slot.
__global__ __launch_bounds__(THREADS) void accum_kernel(
    const float* __restrict__ x,
    const int*   __restrict__ idx)
{
    const int n    = blockIdx.x;
    const int g    = idx[n];
    const int warp = threadIdx.x >> 5;
    const int lane = threadIdx.x & 31;

    if (threadIdx.x == 0) atomicAdd(&g_cnt[g], 1);

    const float* __restrict__ xn = x + (size_t)n * (N_CHAN * HW);
    float* __restrict__ acc_g = &g_acc[g * N_CHAN];

    // Each warp handles channels m = warp, warp+8, ... (64 per warp).
    // Unroll by 2 for memory-level parallelism.
    #pragma unroll 2
    for (int m = warp; m < N_CHAN; m += WARPS) {
        const float* __restrict__ row = xn + m * HW;
        float s = row[lane];                       // lanes 0..31 -> elems 0..31
        if (lane < HW - 32) s += row[32 + lane];   // lanes 0..16 -> elems 32..48
        // warp tree-reduce
        s += __shfl_down_sync(0xFFFFFFFFu, s, 16);
        s += __shfl_down_sync(0xFFFFFFFFu, s, 8);
        s += __shfl_down_sync(0xFFFFFFFFu, s, 4);
        s += __shfl_down_sync(0xFFFFFFFFu, s, 2);
        s += __shfl_down_sync(0xFFFFFFFFu, s, 1);
        if (lane == 0) atomicAdd(&acc_g[m], s);
    }
}

// Kernel 2: finalize -> out[g, m] = acc[g, m] / (cnt[g] * 49)
__global__ void finalize_kernel(float* __restrict__ out) {
    int i = blockIdx.x * blockDim.x + threadIdx.x;
    if (i < N_GROUPS * N_CHAN) {
        int g = i / N_CHAN;
        float denom = (float)g_cnt[g] * (float)HW;
        out[i] = g_acc[i] / denom;
    }
}

extern "C" void kernel_launch(void* const* d_in, const int* in_sizes, int n_in,
                              void* d_out, int out_size)
{
    const float* x   = (const float*)d_in[0];
    const int*   idx = (const int*)d_in[1];
    float*       out = (float*)d_out;

    (void)in_sizes; (void)n_in; (void)out_size;

    const int total = N_GROUPS * N_CHAN;
    zero_kernel<<<(total + THREADS - 1) / THREADS, THREADS>>>();
    accum_kernel<<<N_SAMPLES, THREADS>>>(x, idx);
    finalize_kernel<<<(total + THREADS - 1) / THREADS, THREADS>>>(out);
}

// round 2
// speedup vs baseline: 1.5937x; 1.5937x over previous
#include <cuda_runtime.h>

#define N_SAMPLES   2048
#define N_CHAN      512
#define HW          49
#define N_GROUPS    64
#define THREADS     256
#define WARPS       (THREADS / 32)
#define CH_PER_WARP (N_CHAN / WARPS)   // 64
#define BATCH       8                  // channels loaded per batch

// Scratch accumulators (device globals: zero-initialized at module load;
// finalize_kernel resets them after each use so every graph replay starts
// from zero without a separate zeroing launch).
__device__ float g_acc[N_GROUPS * N_CHAN];
__device__ int   g_cnt[N_GROUPS];

// One block per sample. Each warp owns a contiguous 64-channel block and
// processes it in batches of 8 channels: 16 front-batched LDGs (high MLP),
// then 8 independent shuffle-reduce chains, then 8 lane-0 atomics.
__global__ __launch_bounds__(THREADS) void accum_kernel(
    const float* __restrict__ x,
    const int*   __restrict__ idx)
{
    const int n    = blockIdx.x;
    const int g    = __ldg(&idx[n]);
    const int warp = threadIdx.x >> 5;
    const int lane = threadIdx.x & 31;

    if (threadIdx.x == 0) atomicAdd(&g_cnt[g], 1);

    const float* __restrict__ xn = x + (size_t)n * (N_CHAN * HW);
    float* __restrict__ acc_g = &g_acc[g * N_CHAN];

    const int m0 = warp * CH_PER_WARP;

    #pragma unroll 2
    for (int b = 0; b < CH_PER_WARP; b += BATCH) {
        float va[BATCH], vb[BATCH];
        // Front-batched loads: 16 independent LDGs in flight per batch.
        #pragma unroll
        for (int k = 0; k < BATCH; k++) {
            const float* __restrict__ row = xn + (m0 + b + k) * HW;
            va[k] = row[lane];
            vb[k] = (lane < HW - 32) ? row[32 + lane] : 0.0f;
        }
        // Independent reduce chains — pipelined across k, no load gating.
        #pragma unroll
        for (int k = 0; k < BATCH; k++) {
            float s = va[k] + vb[k];
            s += __shfl_down_sync(0xFFFFFFFFu, s, 16);
            s += __shfl_down_sync(0xFFFFFFFFu, s, 8);
            s += __shfl_down_sync(0xFFFFFFFFu, s, 4);
            s += __shfl_down_sync(0xFFFFFFFFu, s, 2);
            s += __shfl_down_sync(0xFFFFFFFFu, s, 1);
            if (lane == 0) atomicAdd(&acc_g[m0 + b + k], s);
        }
    }
}

// One block per group (64 blocks x 512 threads). Reads acc + count, writes
// the mean, then resets the scratch for the next replay. The count reset is
// after __syncthreads so all readers in this block have consumed it.
__global__ __launch_bounds__(N_CHAN) void finalize_kernel(float* __restrict__ out) {
    const int g = blockIdx.x;
    const int m = threadIdx.x;
    const int i = g * N_CHAN + m;

    const int   c = g_cnt[g];
    const float v = g_acc[i];
    out[i] = v / ((float)c * (float)HW);

    g_acc[i] = 0.0f;           // own element: safe to reset immediately
    __syncthreads();           // everyone has read g_cnt[g]
    if (m == 0) g_cnt[g] = 0;
}

extern "C" void kernel_launch(void* const* d_in, const int* in_sizes, int n_in,
                              void* d_out, int out_size)
{
    const float* x   = (const float*)d_in[0];
    const int*   idx = (const int*)d_in[1];
    float*       out = (float*)d_out;

    (void)in_sizes; (void)n_in; (void)out_size;

    accum_kernel<<<N_SAMPLES, THREADS>>>(x, idx);
    finalize_kernel<<<N_GROUPS, N_CHAN>>>(out);
}